// round 6
// baseline (speedup 1.0000x reference)
#include <cuda_runtime.h>
#include <cuda_bf16.h>
#include <cstdint>

#define TSTEPS 500
#define BATCH  64
#define INDIM  440
#define INPAD  448
#define HID    1024
#define OUTDIM 1944
#define ROWS   (TSTEPS * BATCH)   // 32000

// ---------------------------------------------------------------------------
// Scratch (static device globals; no runtime allocation allowed)
// ---------------------------------------------------------------------------
__device__ __align__(16) __nv_bfloat16 g_act[(size_t)ROWS * HID];   // activations (bf16 spikes)
__device__ __align__(16) float         g_ws [(size_t)ROWS * HID];   // pre-scan dense outputs
__device__ __align__(16) __nv_bfloat16 g_W0hi[HID * INPAD];
__device__ __align__(16) __nv_bfloat16 g_W0lo[HID * INPAD];
__device__ __align__(16) __nv_bfloat16 g_Wshi[3 * HID * HID];
__device__ __align__(16) __nv_bfloat16 g_Wslo[3 * HID * HID];
__device__ __align__(16) __nv_bfloat16 g_Wfhi[OUTDIM * HID];

// ---------------------------------------------------------------------------
// Weight split: w -> bf16 hi + bf16 lo (residual), with K padding zeroed
// ---------------------------------------------------------------------------
__global__ void split_weights_kernel(const float* __restrict__ W,
                                     __nv_bfloat16* __restrict__ hi,
                                     __nv_bfloat16* __restrict__ lo,
                                     int rows, int cols, int colsPad) {
    long long idx = (long long)blockIdx.x * blockDim.x + threadIdx.x;
    long long total = (long long)rows * colsPad;
    if (idx >= total) return;
    int r = (int)(idx / colsPad);
    int c = (int)(idx % colsPad);
    float w = (c < cols) ? W[(long long)r * cols + c] : 0.0f;
    __nv_bfloat16 h = __float2bfloat16(w);
    hi[idx] = h;
    if (lo) lo[idx] = __float2bfloat16(w - __bfloat162float(h));
}

// ---------------------------------------------------------------------------
// Input FSQ scan: vmem += x; q = clip(rint(vmem),0,7); out=q; vmem -= q
// One thread per (b, i) channel, sequential over T. Padded cols write 0.
// ---------------------------------------------------------------------------
__global__ void input_scan_kernel(const float* __restrict__ xs,
                                  __nv_bfloat16* __restrict__ act) {
    int tid = blockIdx.x * blockDim.x + threadIdx.x;
    if (tid >= BATCH * INPAD) return;
    int b = tid / INPAD, i = tid % INPAD;
    __nv_bfloat16* op = act + (size_t)b * INPAD + i;
    const int strideO = BATCH * INPAD;
    if (i >= INDIM) {
        __nv_bfloat16 z = __float2bfloat16(0.0f);
        for (int t = 0; t < TSTEPS; t++) op[t * strideO] = z;
        return;
    }
    const float* xp = xs + (size_t)b * INDIM + i;
    const int strideX = BATCH * INDIM;
    float vmem = 0.0f;
    for (int t = 0; t < TSTEPS; t += 4) {
        float x0 = xp[(t + 0) * strideX];
        float x1 = xp[(t + 1) * strideX];
        float x2 = xp[(t + 2) * strideX];
        float x3 = xp[(t + 3) * strideX];
#define ISTEP(X, TT) { vmem = __fadd_rn(vmem, (X)); \
        float q = fminf(7.0f, fmaxf(0.0f, rintf(vmem))); \
        op[(TT) * strideO] = __float2bfloat16(q); \
        vmem = __fsub_rn(vmem, q); }
        ISTEP(x0, t + 0) ISTEP(x1, t + 1) ISTEP(x2, t + 2) ISTEP(x3, t + 3)
#undef ISTEP
    }
}

// ---------------------------------------------------------------------------
// LIF scan: syn = w + tau*syn; vmem += syn; q = clip(rint(vmem),0,7); vmem -= q
// One thread per (b, h) channel.
// ---------------------------------------------------------------------------
__global__ void lif_scan_kernel(const float* __restrict__ ws,
                                const float* __restrict__ taus,
                                __nv_bfloat16* __restrict__ act) {
    int tid = blockIdx.x * blockDim.x + threadIdx.x;
    if (tid >= BATCH * HID) return;
    int b = tid / HID, h = tid % HID;
    float tau = taus[h];
    const float* wp = ws + (size_t)b * HID + h;
    __nv_bfloat16* op = act + (size_t)b * HID + h;
    const int stride = BATCH * HID;
    float syn = 0.0f, vmem = 0.0f;
    for (int t = 0; t < TSTEPS; t += 4) {
        float w0 = wp[(t + 0) * stride];
        float w1 = wp[(t + 1) * stride];
        float w2 = wp[(t + 2) * stride];
        float w3 = wp[(t + 3) * stride];
#define LSTEP(W, TT) { syn = __fadd_rn((W), __fmul_rn(tau, syn)); \
        vmem = __fadd_rn(vmem, syn); \
        float q = fminf(7.0f, fmaxf(0.0f, rintf(vmem))); \
        op[(TT) * stride] = __float2bfloat16(q); \
        vmem = __fsub_rn(vmem, q); }
        LSTEP(w0, t + 0) LSTEP(w1, t + 1) LSTEP(w2, t + 2) LSTEP(w3, t + 3)
#undef LSTEP
    }
}

// ---------------------------------------------------------------------------
// GEMM: C[M,N] = A[M,K](bf16) * (Bhi+Blo)[N,K](bf16)^T, fused BN epilogue.
// mma.sync m16n8k16 bf16, 128x128x32 CTA tile, 3-stage cp.async pipeline.
// ---------------------------------------------------------------------------
#define BM 128
#define BN 128
#define BK 32
#define GSTAGES 3
#define LDS_ROW 40                          // halves per smem row (32 + 8 pad, conflict-free)
#define STAGE_ONE_BYTES (128 * LDS_ROW * 2) // 10240 per matrix
#define STAGE_BYTES (3 * STAGE_ONE_BYTES)   // A | Bhi | Blo
#define GEMM_SMEM (GSTAGES * STAGE_BYTES)   // 92160

__device__ __forceinline__ void cp_async16(uint32_t dst, const void* src, bool pred) {
    int bytes = pred ? 16 : 0;
    asm volatile("cp.async.cg.shared.global [%0], [%1], 16, %2;\n"
                 :: "r"(dst), "l"(src), "r"(bytes));
}
__device__ __forceinline__ void ldm4(uint32_t* r, uint32_t addr) {
    asm volatile("ldmatrix.sync.aligned.m8n8.x4.shared.b16 {%0,%1,%2,%3}, [%4];\n"
                 : "=r"(r[0]), "=r"(r[1]), "=r"(r[2]), "=r"(r[3]) : "r"(addr));
}
__device__ __forceinline__ void mma_bf16(float* c, const uint32_t* a, uint32_t b0, uint32_t b1) {
    asm volatile("mma.sync.aligned.m16n8k16.row.col.f32.bf16.bf16.f32 "
                 "{%0,%1,%2,%3}, {%4,%5,%6,%7}, {%8,%9}, {%0,%1,%2,%3};\n"
                 : "+f"(c[0]), "+f"(c[1]), "+f"(c[2]), "+f"(c[3])
                 : "r"(a[0]), "r"(a[1]), "r"(a[2]), "r"(a[3]), "r"(b0), "r"(b1));
}

template <bool HAS_LO>
__global__ void __launch_bounds__(256)
gemm_bn_kernel(const __nv_bfloat16* __restrict__ A,
               const __nv_bfloat16* __restrict__ Bhi,
               const __nv_bfloat16* __restrict__ Blo,
               float* __restrict__ C,
               int N, int K,
               const float* __restrict__ gamma,
               const float* __restrict__ beta) {
    extern __shared__ __align__(16) __nv_bfloat16 smem_buf[];
    const int tid = threadIdx.x;
    const int lane = tid & 31, warp = tid >> 5;
    const int wm = warp >> 1;      // 0..3  -> 32 rows of M each
    const int wn = warp & 1;       // 0..1  -> 64 cols of N each
    const int m0 = blockIdx.x * BM;
    const int n0 = blockIdx.y * BN;
    const int KT = K / BK;
    const uint32_t sbase = (uint32_t)__cvta_generic_to_shared(smem_buf);

    // ldmatrix per-lane offsets (matrix idx = lane>>3)
    const int lm   = lane & 7;
    const int mat  = lane >> 3;
    const int roff = ((mat & 1) << 3) | lm;   // +0 / +8 row
    const int koff = (mat >> 1) << 3;         // +0 / +8 col (halves)

    float acc[2][8][4] = {};

    auto issue_stage = [&](int kt, int s) {
        if (kt < KT) {
            const int kk = kt * BK;
            const uint32_t sA  = sbase + s * STAGE_BYTES;
            const uint32_t sBh = sA + STAGE_ONE_BYTES;
            const uint32_t sBl = sBh + STAGE_ONE_BYTES;
#pragma unroll
            for (int i = 0; i < 2; i++) {
                int c = tid + i * 256;
                int r = c >> 2, col = c & 3;
                uint32_t dst = sA + (uint32_t)(r * LDS_ROW + col * 8) * 2;
                cp_async16(dst, A + (size_t)(m0 + r) * K + kk + col * 8, true);
            }
#pragma unroll
            for (int i = 0; i < 2; i++) {
                int c = tid + i * 256;
                int r = c >> 2, col = c & 3;
                bool pred = (n0 + r) < N;
                int rr = pred ? (n0 + r) : 0;
                uint32_t dst = sBh + (uint32_t)(r * LDS_ROW + col * 8) * 2;
                cp_async16(dst, Bhi + (size_t)rr * K + kk + col * 8, pred);
                if (HAS_LO) {
                    uint32_t dstl = sBl + (uint32_t)(r * LDS_ROW + col * 8) * 2;
                    cp_async16(dstl, Blo + (size_t)rr * K + kk + col * 8, pred);
                }
            }
        }
        asm volatile("cp.async.commit_group;\n" ::);
    };

    auto compute_stage = [&](int s) {
        const uint32_t aB  = sbase + s * STAGE_BYTES;
        const uint32_t bhB = aB + STAGE_ONE_BYTES;
        const uint32_t blB = bhB + STAGE_ONE_BYTES;
#pragma unroll
        for (int k16 = 0; k16 < 2; k16++) {
            uint32_t afr[2][4];
#pragma unroll
            for (int mi = 0; mi < 2; mi++)
                ldm4(afr[mi], aB + (uint32_t)((wm * 32 + mi * 16 + roff) * LDS_ROW + k16 * 16 + koff) * 2);
#pragma unroll
            for (int nj = 0; nj < 4; nj++) {
                uint32_t boff = (uint32_t)((wn * 64 + nj * 16 + roff) * LDS_ROW + k16 * 16 + koff) * 2;
                uint32_t bfr[4];
                ldm4(bfr, bhB + boff);
                mma_bf16(acc[0][2 * nj + 0], afr[0], bfr[0], bfr[2]);
                mma_bf16(acc[1][2 * nj + 0], afr[1], bfr[0], bfr[2]);
                mma_bf16(acc[0][2 * nj + 1], afr[0], bfr[1], bfr[3]);
                mma_bf16(acc[1][2 * nj + 1], afr[1], bfr[1], bfr[3]);
                if (HAS_LO) {
                    uint32_t lfr[4];
                    ldm4(lfr, blB + boff);
                    mma_bf16(acc[0][2 * nj + 0], afr[0], lfr[0], lfr[2]);
                    mma_bf16(acc[1][2 * nj + 0], afr[1], lfr[0], lfr[2]);
                    mma_bf16(acc[0][2 * nj + 1], afr[0], lfr[1], lfr[3]);
                    mma_bf16(acc[1][2 * nj + 1], afr[1], lfr[1], lfr[3]);
                }
            }
        }
    };

    // prologue: stages 0..GSTAGES-2
#pragma unroll
    for (int s = 0; s < GSTAGES - 1; s++) issue_stage(s, s);

    for (int kt = 0; kt < KT; kt++) {
        asm volatile("cp.async.wait_group 1;\n" ::);
        __syncthreads();
        compute_stage(kt % GSTAGES);
        issue_stage(kt + GSTAGES - 1, (kt + GSTAGES - 1) % GSTAGES);
    }
    asm volatile("cp.async.wait_group 0;\n" ::);

    // Epilogue: BN (x * gamma/sqrt(1+eps) + beta), write fp32
    const float inv = rsqrtf(1.0f + 1e-5f);
    const int qr = lane >> 2;
    const int qc = (lane & 3) << 1;
#pragma unroll
    for (int ni = 0; ni < 8; ni++) {
        int n = n0 + wn * 64 + ni * 8 + qc;
        if (n >= N) continue;
        float g0 = gamma[n] * inv, b0 = beta[n];
        bool has2 = (n + 1 < N);
        float g1 = has2 ? gamma[n + 1] * inv : 0.0f;
        float b1 = has2 ? beta[n + 1] : 0.0f;
#pragma unroll
        for (int mi = 0; mi < 2; mi++) {
#pragma unroll
            for (int h = 0; h < 2; h++) {
                int row = m0 + wm * 32 + mi * 16 + qr + h * 8;
                float v0 = fmaf(acc[mi][ni][h * 2 + 0], g0, b0);
                float v1 = fmaf(acc[mi][ni][h * 2 + 1], g1, b1);
                float* cp = C + (size_t)row * N + n;
                if (has2) *reinterpret_cast<float2*>(cp) = make_float2(v0, v1);
                else      cp[0] = v0;
            }
        }
    }
}

// ---------------------------------------------------------------------------
// log-softmax over rows of [ROWS, OUTDIM], in place
// ---------------------------------------------------------------------------
__global__ void __launch_bounds__(256) logsoftmax_kernel(float* __restrict__ out) {
    __shared__ float sv[OUTDIM];
    __shared__ float red[9];
    const int tid = threadIdx.x, lane = tid & 31, warp = tid >> 5;
    float* p = out + (size_t)blockIdx.x * OUTDIM;

    float mx = -3.4e38f;
    for (int i = tid; i < OUTDIM; i += 256) { float v = p[i]; sv[i] = v; mx = fmaxf(mx, v); }
#pragma unroll
    for (int o = 16; o; o >>= 1) mx = fmaxf(mx, __shfl_xor_sync(0xffffffffu, mx, o));
    if (lane == 0) red[warp] = mx;
    __syncthreads();
    if (warp == 0) {
        float v = (lane < 8) ? red[lane] : -3.4e38f;
#pragma unroll
        for (int o = 4; o; o >>= 1) v = fmaxf(v, __shfl_xor_sync(0xffffffffu, v, o));
        if (lane == 0) red[8] = v;
    }
    __syncthreads();
    mx = red[8];

    float s = 0.0f;
    for (int i = tid; i < OUTDIM; i += 256) s += expf(sv[i] - mx);
#pragma unroll
    for (int o = 16; o; o >>= 1) s += __shfl_xor_sync(0xffffffffu, s, o);
    __syncthreads();   // protect red[] reuse
    if (lane == 0) red[warp] = s;
    __syncthreads();
    if (warp == 0) {
        float v = (lane < 8) ? red[lane] : 0.0f;
#pragma unroll
        for (int o = 4; o; o >>= 1) v += __shfl_xor_sync(0xffffffffu, v, o);
        if (lane == 0) red[8] = v;
    }
    __syncthreads();
    float lse = mx + logf(red[8]);
    for (int i = tid; i < OUTDIM; i += 256) p[i] = sv[i] - lse;
}

// ---------------------------------------------------------------------------
// Launch sequence
// ---------------------------------------------------------------------------
extern "C" void kernel_launch(void* const* d_in, const int* in_sizes, int n_in,
                              void* d_out, int out_size) {
    const float* xs   = (const float*)d_in[0];   // [500,64,440]
    const float* W0   = (const float*)d_in[1];   // [1024,440]
    const float* Ws   = (const float*)d_in[2];   // [3,1024,1024]
    const float* taus = (const float*)d_in[3];   // [4,1024]
    const float* bng  = (const float*)d_in[4];   // [4,1024]
    const float* bnb  = (const float*)d_in[5];   // [4,1024]
    const float* Wf   = (const float*)d_in[6];   // [1944,1024]
    const float* fg   = (const float*)d_in[7];   // [1944]
    const float* fb   = (const float*)d_in[8];   // [1944]
    float* out = (float*)d_out;

    void* p;
    cudaGetSymbolAddress(&p, g_act);  __nv_bfloat16* act  = (__nv_bfloat16*)p;
    cudaGetSymbolAddress(&p, g_ws);   float*         ws   = (float*)p;
    cudaGetSymbolAddress(&p, g_W0hi); __nv_bfloat16* w0hi = (__nv_bfloat16*)p;
    cudaGetSymbolAddress(&p, g_W0lo); __nv_bfloat16* w0lo = (__nv_bfloat16*)p;
    cudaGetSymbolAddress(&p, g_Wshi); __nv_bfloat16* wshi = (__nv_bfloat16*)p;
    cudaGetSymbolAddress(&p, g_Wslo); __nv_bfloat16* wslo = (__nv_bfloat16*)p;
    cudaGetSymbolAddress(&p, g_Wfhi); __nv_bfloat16* wfhi = (__nv_bfloat16*)p;

    cudaFuncSetAttribute(gemm_bn_kernel<true>,  cudaFuncAttributeMaxDynamicSharedMemorySize, GEMM_SMEM);
    cudaFuncSetAttribute(gemm_bn_kernel<false>, cudaFuncAttributeMaxDynamicSharedMemorySize, GEMM_SMEM);

    // weight splits (idempotent; cheap)
    split_weights_kernel<<<(HID * INPAD + 255) / 256, 256>>>(W0, w0hi, w0lo, HID, INDIM, INPAD);
    split_weights_kernel<<<(3 * HID * HID + 255) / 256, 256>>>(Ws, wshi, wslo, 3 * HID, HID, HID);
    split_weights_kernel<<<(OUTDIM * HID + 255) / 256, 256>>>(Wf, wfhi, nullptr, OUTDIM, HID, HID);

    // input FSQ scan -> act [32000, 448] bf16
    input_scan_kernel<<<(BATCH * INPAD) / 64, 64>>>(xs, act);

    dim3 gh(ROWS / BM, HID / BN);   // (250, 8)

    // layer 0
    gemm_bn_kernel<true><<<gh, 256, GEMM_SMEM>>>(act, w0hi, w0lo, ws, HID, INPAD, bng, bnb);
    lif_scan_kernel<<<(BATCH * HID) / 128, 128>>>(ws, taus, act);

    // layers 1..3
    for (int l = 1; l < 4; l++) {
        gemm_bn_kernel<true><<<gh, 256, GEMM_SMEM>>>(
            act, wshi + (size_t)(l - 1) * HID * HID, wslo + (size_t)(l - 1) * HID * HID,
            ws, HID, HID, bng + l * HID, bnb + l * HID);
        lif_scan_kernel<<<(BATCH * HID) / 128, 128>>>(ws, taus + l * HID, act);
    }

    // final projection -> d_out [32000, 1944] fp32 (bf16-hi only; no quantization downstream)
    dim3 gf(ROWS / BM, (OUTDIM + BN - 1) / BN);  // (250, 16)
    gemm_bn_kernel<false><<<gf, 256, GEMM_SMEM>>>(act, wfhi, nullptr, out, OUTDIM, HID, fg, fb);

    // in-place log-softmax per row
    logsoftmax_kernel<<<ROWS, 256>>>(out);
}